// round 6
// baseline (speedup 1.0000x reference)
#include <cuda_runtime.h>
#include <cfloat>
#include <math.h>

#define Bn 64
#define Dn 256
#define Ln 4096
#define DKn 128
#define LN_EPS 1e-6f
#define EPS_CLIP 1e-10f

#define CH1 64                 // l-chunk per tile block
#define NCH (Ln / CH1)         // 64 chunks per batch

// ---------------- scratch (static device globals; no allocation) ----------------
__device__ float g_mu[Bn * Ln];
__device__ float g_rsig[Bn * Ln];
__device__ float g_PU[Bn * NCH * 3 * Dn];   // pass1 per-chunk partials U1,U2,U3
__device__ float g_PR[Bn * NCH * 3 * Dn];   // fused per-chunk partials R1,R2,R3
__device__ float g_Psmr[Bn * NCH];
__device__ float g_Ps22[Bn * NCH];
__device__ float g_Pml[Bn * NCH];           // chunk-local score max
__device__ float g_Pse[Bn * NCH];           // sum of e
__device__ float g_Pa[Bn * NCH];            // sum of e*mu*rsig
__device__ float g_Pm2[Bn * NCH];           // sum of e*(mu*rsig)^2
__device__ float g_gp[Bn * Dn];
__device__ float g_corr[Bn * Dn];
__device__ float g_Cb[Bn], g_Gp[Bn];

// ---------------- reduction helpers ----------------
__device__ __forceinline__ float warpSum(float v) {
#pragma unroll
    for (int o = 16; o; o >>= 1) v += __shfl_xor_sync(0xffffffffu, v, o);
    return v;
}
__device__ __forceinline__ float warpMax(float v) {
#pragma unroll
    for (int o = 16; o; o >>= 1) v = fmaxf(v, __shfl_xor_sync(0xffffffffu, v, o));
    return v;
}
__device__ __forceinline__ float bSum(float v) {
    __shared__ float sh[32];
    int lane = threadIdx.x & 31, w = threadIdx.x >> 5;
    int nw = (blockDim.x + 31) >> 5;
    v = warpSum(v);
    if (lane == 0) sh[w] = v;
    __syncthreads();
    if (w == 0) {
        float x = (lane < nw) ? sh[lane] : 0.0f;
        x = warpSum(x);
        if (lane == 0) sh[0] = x;
    }
    __syncthreads();
    float r = sh[0];
    __syncthreads();
    return r;
}

// ---------------- 1. fused: LN stats + unweighted rowsum partials ----------------
__global__ void __launch_bounds__(512) k_pass1(const float* __restrict__ v) {
    extern __shared__ float sm[];
    float* tile = sm;                       // 16384
    float* s_mu = tile + Dn * CH1;          // 64
    float* s_rs = s_mu + CH1;               // 64
    float* s_mr = s_rs + CH1;               // 64
    float* s_m2 = s_mr + CH1;               // 64
    float* sA   = s_m2 + CH1;               // 64*33
    float* sQ   = sA + 64 * 33;             // 64*33

    int t = threadIdx.x;                    // 512
    int b = blockIdx.x >> 6;                // NCH == 64
    int ch = blockIdx.x & 63;
    int l0 = ch * CH1;
    int dg = t >> 4;                        // 0..31
    int lv = t & 15;                        // float4 group within 64 l's

    const float* vbase = v + (size_t)b * Dn * Ln + l0 + lv * 4;
    float s0 = 0.f, s1 = 0.f, s2 = 0.f, s3 = 0.f;
    float q0 = 0.f, q1 = 0.f, q2 = 0.f, q3 = 0.f;
#pragma unroll
    for (int it = 0; it < 8; it++) {
        int d = it * 32 + dg;
        float4 x = *reinterpret_cast<const float4*>(vbase + (size_t)d * Ln);
        *reinterpret_cast<float4*>(&tile[d * CH1 + lv * 4]) = x;
        s0 += x.x; s1 += x.y; s2 += x.z; s3 += x.w;
        q0 = fmaf(x.x, x.x, q0);
        q1 = fmaf(x.y, x.y, q1);
        q2 = fmaf(x.z, x.z, q2);
        q3 = fmaf(x.w, x.w, q3);
    }
    sA[(lv * 4 + 0) * 33 + dg] = s0;
    sA[(lv * 4 + 1) * 33 + dg] = s1;
    sA[(lv * 4 + 2) * 33 + dg] = s2;
    sA[(lv * 4 + 3) * 33 + dg] = s3;
    sQ[(lv * 4 + 0) * 33 + dg] = q0;
    sQ[(lv * 4 + 1) * 33 + dg] = q1;
    sQ[(lv * 4 + 2) * 33 + dg] = q2;
    sQ[(lv * 4 + 3) * 33 + dg] = q3;
    __syncthreads();

    if (t < CH1) {
        float ss = 0.f, qq = 0.f;
#pragma unroll
        for (int g = 0; g < 32; g++) {
            ss += sA[t * 33 + g];
            qq += sQ[t * 33 + g];
        }
        float mu = ss * (1.0f / Dn);
        float var = qq * (1.0f / Dn) - mu * mu;
        float rs = rsqrtf(var + LN_EPS);
        s_mu[t] = mu;
        s_rs[t] = rs;
        g_mu[b * Ln + l0 + t] = mu;
        g_rsig[b * Ln + l0 + t] = rs;
        float mr = mu * rs;
        s_mr[t] = mr;
        s_m2[t] = mr * mr;
    }
    __syncthreads();
    int bc = blockIdx.x;
    if (t < 32) {
        float a = s_mr[t] + s_mr[32 + t];
        a = warpSum(a);
        if (t == 0) g_Psmr[bc] = a;
    } else if (t < 64) {
        int u = t - 32;
        float a = s_m2[u] + s_m2[32 + u];
        a = warpSum(a);
        if (u == 0) g_Ps22[bc] = a;
    }
    __syncthreads();

    int w = t >> 5, lane = t & 31;          // 16 warps
#pragma unroll
    for (int i = 0; i < 16; i++) {
        int d = i * 16 + w;
        float u1 = 0.f, u2 = 0.f, u3 = 0.f;
#pragma unroll
        for (int j = 0; j < 2; j++) {
            int l = j * 32 + lane;
            float x = tile[d * CH1 + l];
            float r = s_rs[l], a = s_mu[l];
            float xr = x * r;
            u1 += xr;
            u2 = fmaf(xr, xr, u2);
            u3 = fmaf(xr, a * r, u3);
        }
        u1 = warpSum(u1);
        u2 = warpSum(u2);
        u3 = warpSum(u3);
        if (lane == 0) {
            g_PU[(bc * 3 + 0) * Dn + d] = u1;
            g_PU[(bc * 3 + 1) * Dn + d] = u2;
            g_PU[(bc * 3 + 2) * Dn + d] = u3;
        }
    }
}

// ---------------- 2. per batch: reduce partials, batch mean/std, q, p ----------------
__global__ void k_qp(const float* __restrict__ wk, const float* __restrict__ wq,
                     const float* __restrict__ ln_g, const float* __restrict__ ln_b) {
    int b = blockIdx.x;
    int t = threadIdx.x;  // 256
    int w = t >> 5, lane = t & 31;
    __shared__ float ms[2 * Dn];
    __shared__ float qv[DKn];
    __shared__ float s_sc[2];

    float U1 = 0.f, U2 = 0.f, U3 = 0.f;
#pragma unroll 8
    for (int c = 0; c < NCH; c++) {
        int bc = b * NCH + c;
        U1 += g_PU[(bc * 3 + 0) * Dn + t];
        U2 += g_PU[(bc * 3 + 1) * Dn + t];
        U3 += g_PU[(bc * 3 + 2) * Dn + t];
    }
    if (w == 0) {
        float a = g_Psmr[b * NCH + lane] + g_Psmr[b * NCH + 32 + lane];
        a = warpSum(a);
        if (lane == 0) s_sc[0] = a;
    } else if (w == 1) {
        float a = g_Ps22[b * NCH + lane] + g_Ps22[b * NCH + 32 + lane];
        a = warpSum(a);
        if (lane == 0) s_sc[1] = a;
    }
    __syncthreads();
    float smr = s_sc[0], sm2r2 = s_sc[1];

    {
        int d = t;
        float g = ln_g[d], be = ln_b[d];
        float S1 = g * (U1 - smr) + (float)Ln * be;
        float S2 = g * g * (U2 - 2.0f * U3 + sm2r2) + 2.0f * g * be * (U1 - smr) + (float)Ln * be * be;
        float mean = S1 * (1.0f / Ln);
        float var = S2 * (1.0f / Ln) - mean * mean;
        float sd = sqrtf(fmaxf(var, EPS_CLIP));
        ms[d] = mean;
        ms[Dn + d] = sd;
    }
    __syncthreads();

#pragma unroll
    for (int i = 0; i < 16; i++) {
        int k = w * 16 + i;
        float acc = 0.f;
        const float* wr = wq + (size_t)k * 2 * Dn;
#pragma unroll
        for (int e = 0; e < 16; e++)
            acc = fmaf(wr[e * 32 + lane], ms[e * 32 + lane], acc);
        acc = warpSum(acc);
        if (lane == 0) qv[k] = acc;
    }
    __syncthreads();

    float p = 0.f;
#pragma unroll 8
    for (int k2 = 0; k2 < DKn; k2++) p = fmaf(wk[k2 * Dn + t], qv[k2], p);
    p *= rsqrtf((float)DKn);

    float gp = ln_g[t] * p;
    g_gp[b * Dn + t] = gp;
    float cb = bSum(ln_b[t] * p);
    float gpsum = bSum(gp);
    if (t == 0) { g_Cb[b] = cb; g_Gp[b] = gpsum; }
}

// ---------------- 3. FUSED scores + local softmax + weighted rowsum partials ----------------
// One block per (b, 64-l chunk). Reads its v tile ONCE.
//   Phase A: tile load + per-l dot with gp  -> scores
//   local max -> e_l = exp(s - mloc), coefficient arrays c1,c2,c3
//   Phase B: per-d partial sums R1,R2,R3 with e-weights
__global__ void __launch_bounds__(512) k_fused(const float* __restrict__ v) {
    extern __shared__ float sm[];
    float* tile = sm;                       // 16384
    float* s_gp = tile + Dn * CH1;          // 256
    float* s_mu = s_gp + Dn;                // 64
    float* s_rs = s_mu + CH1;               // 64
    float* s_c1 = s_rs + CH1;               // 64
    float* s_c2 = s_c1 + CH1;               // 64
    float* s_c3 = s_c2 + CH1;               // 64
    float* s_s  = s_c3 + CH1;               // 64 (scores, then e)
    float* s_ml = s_s + CH1;                // 1
    float* sA   = s_ml + 1;                 // 64*33 dot-reduction scratch

    int t = threadIdx.x;                    // 512
    int b = blockIdx.x >> 6;
    int ch = blockIdx.x & 63;
    int l0 = ch * CH1;
    int bc = blockIdx.x;
    int dg = t >> 4;                        // 0..31
    int lv = t & 15;

    if (t < Dn) s_gp[t] = g_gp[b * Dn + t];
    if (t >= 256 && t < 320) s_mu[t - 256] = g_mu[b * Ln + l0 + (t - 256)];
    if (t >= 320 && t < 384) s_rs[t - 320] = g_rsig[b * Ln + l0 + (t - 320)];
    __syncthreads();

    // Phase A: load tile, accumulate per-l dot over this thread's 8 d's
    const float* vbase = v + (size_t)b * Dn * Ln + l0 + lv * 4;
    float a0 = 0.f, a1 = 0.f, a2 = 0.f, a3 = 0.f;
#pragma unroll
    for (int it = 0; it < 8; it++) {
        int d = it * 32 + dg;
        float4 x = *reinterpret_cast<const float4*>(vbase + (size_t)d * Ln);
        *reinterpret_cast<float4*>(&tile[d * CH1 + lv * 4]) = x;
        float g = s_gp[d];
        a0 = fmaf(x.x, g, a0);
        a1 = fmaf(x.y, g, a1);
        a2 = fmaf(x.z, g, a2);
        a3 = fmaf(x.w, g, a3);
    }
    sA[(lv * 4 + 0) * 33 + dg] = a0;
    sA[(lv * 4 + 1) * 33 + dg] = a1;
    sA[(lv * 4 + 2) * 33 + dg] = a2;
    sA[(lv * 4 + 3) * 33 + dg] = a3;
    __syncthreads();

    if (t < CH1) {
        float dot = 0.f;
#pragma unroll
        for (int g = 0; g < 32; g++) dot += sA[t * 33 + g];
        float mu = s_mu[t], rs = s_rs[t];
        s_s[t] = rs * (dot - mu * g_Gp[b]) + g_Cb[b];
    }
    __syncthreads();

    // local max over 64 scores
    if (t < 32) {
        float m = fmaxf(s_s[t], s_s[32 + t]);
        m = warpMax(m);
        if (t == 0) { s_ml[0] = m; g_Pml[bc] = m; }
    }
    __syncthreads();

    // e and coefficient arrays
    if (t < CH1) {
        float mloc = s_ml[0];
        float e = __expf(s_s[t] - mloc);
        float rs = s_rs[t], mu = s_mu[t];
        float c1 = e * rs;
        float c2 = c1 * rs;
        s_c1[t] = c1;
        s_c2[t] = c2;
        s_c3[t] = c2 * mu;
        s_s[t] = e;                 // overwrite score with e
        float mr = mu * rs;
        sA[t] = e;                  // scratch for scalar reductions
        sA[64 + t] = e * mr;
        sA[128 + t] = e * mr * mr;
    }
    __syncthreads();
    if (t < 32) {
        float a = sA[t] + sA[32 + t];
        a = warpSum(a);
        if (t == 0) g_Pse[bc] = a;
    } else if (t < 64) {
        int u = t - 32;
        float a = sA[64 + u] + sA[96 + u];
        a = warpSum(a);
        if (u == 0) g_Pa[bc] = a;
    } else if (t < 96) {
        int u = t - 64;
        float a = sA[128 + u] + sA[160 + u];
        a = warpSum(a);
        if (u == 0) g_Pm2[bc] = a;
    }
    __syncthreads();

    // Phase B: per-d weighted sums over chunk
    int w = t >> 5, lane = t & 31;          // 16 warps
#pragma unroll
    for (int i = 0; i < 16; i++) {
        int d = i * 16 + w;
        float r1 = 0.f, r2 = 0.f, r3 = 0.f;
#pragma unroll
        for (int j = 0; j < 2; j++) {
            int l = j * 32 + lane;
            float x = tile[d * CH1 + l];
            r1 = fmaf(x, s_c1[l], r1);
            r2 = fmaf(x * x, s_c2[l], r2);
            r3 = fmaf(x, s_c3[l], r3);
        }
        r1 = warpSum(r1);
        r2 = warpSum(r2);
        r3 = warpSum(r3);
        if (lane == 0) {
            g_PR[(bc * 3 + 0) * Dn + d] = r1;
            g_PR[(bc * 3 + 1) * Dn + d] = r2;
            g_PR[(bc * 3 + 2) * Dn + d] = r3;
        }
    }
}

// ---------------- 4. combine partials + att stats -> corr + skip_conn ----------------
__global__ void k_finalize(const float* __restrict__ fcq_w, const float* __restrict__ fc_w,
                           const float* __restrict__ fc_b, const float* __restrict__ ln_g,
                           const float* __restrict__ ln_b, float* __restrict__ out) {
    int b = blockIdx.x;
    int t = threadIdx.x;  // 256
    __shared__ float s_scale[NCH];
    __shared__ float s_M[1];
    __shared__ float am[Dn], as[Dn];

    if (t < 32) {
        float m = fmaxf(g_Pml[b * NCH + t], g_Pml[b * NCH + 32 + t]);
        m = warpMax(m);
        if (t == 0) s_M[0] = m;
    }
    __syncthreads();
    if (t < NCH) s_scale[t] = __expf(g_Pml[b * NCH + t] - s_M[0]);
    __syncthreads();

    float R1 = 0.f, R2 = 0.f, R3 = 0.f;
#pragma unroll 8
    for (int c = 0; c < NCH; c++) {
        int bc = b * NCH + c;
        float sc = s_scale[c];
        R1 = fmaf(g_PR[(bc * 3 + 0) * Dn + t], sc, R1);
        R2 = fmaf(g_PR[(bc * 3 + 1) * Dn + t], sc, R2);
        R3 = fmaf(g_PR[(bc * 3 + 2) * Dn + t], sc, R3);
    }
    float se_p = (t < NCH) ? g_Pse[b * NCH + t] * s_scale[t] : 0.f;
    float a_p  = (t < NCH) ? g_Pa[b * NCH + t] * s_scale[t] : 0.f;
    float m2_p = (t < NCH) ? g_Pm2[b * NCH + t] * s_scale[t] : 0.f;
    float SE = bSum(se_p);
    float Asum = bSum(a_p);
    float M2sum = bSum(m2_p);
    float inv = 1.0f / SE;
    float A = Asum * inv, M2 = M2sum * inv;
    R1 *= inv; R2 *= inv; R3 *= inv;

    {
        int d = t;
        float g = ln_g[d], be = ln_b[d];
        float mean = g * (R1 - A) + be;
        float E2 = g * g * (R2 - 2.0f * R3 + M2) + 2.0f * g * be * (R1 - A) + be * be;
        float var = E2 - mean * mean;
        am[d] = mean;
        as[d] = sqrtf(fmaxf(var, EPS_CLIP));
    }
    __syncthreads();
    {
        int o = t;
        float c = 0.f;
        const float* wr = fcq_w + (size_t)o * Dn;
#pragma unroll 8
        for (int d = 0; d < Dn; d++) c = fmaf(wr[d], am[d], c);
        g_corr[b * Dn + o] = c;
        float sk = fc_b[o];
        const float* fr = fc_w + (size_t)o * 2 * Dn;
#pragma unroll 8
        for (int d = 0; d < Dn; d++) {
            sk = fmaf(fr[d], am[d], sk);
            sk = fmaf(fr[Dn + d], as[d], sk);
        }
        out[(size_t)Bn * Ln * Dn + b * Dn + o] = sk;
    }
}

// ---------------- 5. out1[b,l,o] = v[b,o,l] + corr[b,o]  (128l x 32o tile, streaming) ----------------
__global__ void k_out(const float* __restrict__ v, float* __restrict__ out) {
    __shared__ float tile[32 * 129];
    int b = blockIdx.z;
    int l0 = blockIdx.x * 128;
    int o0 = blockIdx.y * 32;
    int tid = threadIdx.x;          // 256
    int w = tid >> 5, lane = tid & 31;

#pragma unroll
    for (int i = 0; i < 4; i++) {
        int ol = w + 8 * i;
        int o = o0 + ol;
        float c = g_corr[b * Dn + o];
        const float4* vr = reinterpret_cast<const float4*>(v + ((size_t)(b * Dn + o)) * Ln + l0);
        float4 x = __ldcs(vr + lane);
        tile[ol * 129 + lane * 4 + 0] = x.x + c;
        tile[ol * 129 + lane * 4 + 1] = x.y + c;
        tile[ol * 129 + lane * 4 + 2] = x.z + c;
        tile[ol * 129 + lane * 4 + 3] = x.w + c;
    }
    __syncthreads();

    int o4 = tid & 7;
    int lq = tid >> 3;
#pragma unroll
    for (int i = 0; i < 4; i++) {
        int l = i * 32 + lq;
        float4 y;
        y.x = tile[(o4 * 4 + 0) * 129 + l];
        y.y = tile[(o4 * 4 + 1) * 129 + l];
        y.z = tile[(o4 * 4 + 2) * 129 + l];
        y.w = tile[(o4 * 4 + 3) * 129 + l];
        __stcs(reinterpret_cast<float4*>(out + ((size_t)b * Ln + l0 + l) * Dn + o0 + o4 * 4), y);
    }
}

// ---------------- launcher: 5-kernel chain, 3 v-reads + 1 write ----------------
extern "C" void kernel_launch(void* const* d_in, const int* in_sizes, int n_in,
                              void* d_out, int out_size) {
    const float* v     = (const float*)d_in[0];
    const float* ln_g  = (const float*)d_in[1];
    const float* ln_b  = (const float*)d_in[2];
    const float* wk    = (const float*)d_in[3];
    const float* wq    = (const float*)d_in[4];
    const float* fcq_w = (const float*)d_in[5];
    const float* fc_w  = (const float*)d_in[6];
    const float* fc_b  = (const float*)d_in[7];
    float* out = (float*)d_out;

    const int p1_smem = (Dn * CH1 + 4 * CH1 + 2 * 64 * 33) * 4;             // 83200 B
    const int pf_smem = (Dn * CH1 + Dn + 6 * CH1 + 1 + 64 * 33) * 4;        // ~76.5 KB
    cudaFuncSetAttribute(k_pass1, cudaFuncAttributeMaxDynamicSharedMemorySize, p1_smem);
    cudaFuncSetAttribute(k_fused, cudaFuncAttributeMaxDynamicSharedMemorySize, pf_smem);

    k_pass1<<<Bn * NCH, 512, p1_smem>>>(v);
    k_qp<<<Bn, 256>>>(wk, wq, ln_g, ln_b);
    k_fused<<<Bn * NCH, 512, pf_smem>>>(v);
    k_finalize<<<Bn, 256>>>(fcq_w, fc_w, fc_b, ln_g, ln_b, out);
    k_out<<<dim3(Ln / 128, Dn / 32, Bn), 256>>>(v, out);
}

// round 7
// speedup vs baseline: 1.3056x; 1.3056x over previous
#include <cuda_runtime.h>
#include <cfloat>
#include <math.h>

#define Bn 64
#define Dn 256
#define Ln 4096
#define DKn 128
#define LN_EPS 1e-6f
#define EPS_CLIP 1e-10f

#define CH1 64                 // l-chunk per pass1 block
#define NCH (Ln / CH1)         // 64 chunks per batch

// ---------------- scratch (static device globals; no allocation) ----------------
__device__ float g_mu[Bn * Ln];
__device__ float g_rsig[Bn * Ln];
__device__ float g_scores[Bn * Ln];
__device__ float g_w[Bn * Ln];
__device__ float g_PU[Bn * NCH * 3 * Dn];   // per-chunk partials of U1,U2,U3
__device__ float g_Psmr[Bn * NCH];
__device__ float g_Ps22[Bn * NCH];
__device__ float g_R1[Bn * Dn], g_R2[Bn * Dn], g_R3[Bn * Dn];
__device__ float g_gp[Bn * Dn];
__device__ float g_corr[Bn * Dn];
__device__ float g_Cb[Bn], g_Gp[Bn], g_A[Bn], g_M2[Bn];

// ---------------- reduction helpers ----------------
__device__ __forceinline__ float warpSum(float v) {
#pragma unroll
    for (int o = 16; o; o >>= 1) v += __shfl_xor_sync(0xffffffffu, v, o);
    return v;
}
__device__ __forceinline__ float warpMax(float v) {
#pragma unroll
    for (int o = 16; o; o >>= 1) v = fmaxf(v, __shfl_xor_sync(0xffffffffu, v, o));
    return v;
}
__device__ __forceinline__ float bSum(float v) {
    __shared__ float sh[32];
    int lane = threadIdx.x & 31, w = threadIdx.x >> 5;
    int nw = (blockDim.x + 31) >> 5;
    v = warpSum(v);
    if (lane == 0) sh[w] = v;
    __syncthreads();
    if (w == 0) {
        float x = (lane < nw) ? sh[lane] : 0.0f;
        x = warpSum(x);
        if (lane == 0) sh[0] = x;
    }
    __syncthreads();
    float r = sh[0];
    __syncthreads();
    return r;
}
__device__ __forceinline__ float bMax(float v) {
    __shared__ float sh[32];
    int lane = threadIdx.x & 31, w = threadIdx.x >> 5;
    int nw = (blockDim.x + 31) >> 5;
    v = warpMax(v);
    if (lane == 0) sh[w] = v;
    __syncthreads();
    if (w == 0) {
        float x = (lane < nw) ? sh[lane] : -FLT_MAX;
        x = warpMax(x);
        if (lane == 0) sh[0] = x;
    }
    __syncthreads();
    float r = sh[0];
    __syncthreads();
    return r;
}

// ---------------- 1. fused: LN stats + unweighted rowsum partials ----------------
__global__ void __launch_bounds__(512) k_pass1(const float* __restrict__ v) {
    extern __shared__ float sm[];
    float* tile = sm;                       // 16384
    float* s_mu = tile + Dn * CH1;          // 64
    float* s_rs = s_mu + CH1;               // 64
    float* s_mr = s_rs + CH1;               // 64
    float* s_m2 = s_mr + CH1;               // 64
    float* sA   = s_m2 + CH1;               // 64*33
    float* sQ   = sA + 64 * 33;             // 64*33

    int t = threadIdx.x;                    // 512
    int b = blockIdx.x >> 6;                // NCH == 64
    int ch = blockIdx.x & 63;
    int l0 = ch * CH1;
    int dg = t >> 4;                        // 0..31
    int lv = t & 15;                        // float4 group within 64 l's

    const float* vbase = v + (size_t)b * Dn * Ln + l0 + lv * 4;
    float s0 = 0.f, s1 = 0.f, s2 = 0.f, s3 = 0.f;
    float q0 = 0.f, q1 = 0.f, q2 = 0.f, q3 = 0.f;
#pragma unroll
    for (int it = 0; it < 8; it++) {
        int d = it * 32 + dg;
        float4 x = *reinterpret_cast<const float4*>(vbase + (size_t)d * Ln);
        *reinterpret_cast<float4*>(&tile[d * CH1 + lv * 4]) = x;
        s0 += x.x; s1 += x.y; s2 += x.z; s3 += x.w;
        q0 = fmaf(x.x, x.x, q0);
        q1 = fmaf(x.y, x.y, q1);
        q2 = fmaf(x.z, x.z, q2);
        q3 = fmaf(x.w, x.w, q3);
    }
    sA[(lv * 4 + 0) * 33 + dg] = s0;
    sA[(lv * 4 + 1) * 33 + dg] = s1;
    sA[(lv * 4 + 2) * 33 + dg] = s2;
    sA[(lv * 4 + 3) * 33 + dg] = s3;
    sQ[(lv * 4 + 0) * 33 + dg] = q0;
    sQ[(lv * 4 + 1) * 33 + dg] = q1;
    sQ[(lv * 4 + 2) * 33 + dg] = q2;
    sQ[(lv * 4 + 3) * 33 + dg] = q3;
    __syncthreads();

    if (t < CH1) {
        float ss = 0.f, qq = 0.f;
#pragma unroll
        for (int g = 0; g < 32; g++) {
            ss += sA[t * 33 + g];
            qq += sQ[t * 33 + g];
        }
        float mu = ss * (1.0f / Dn);
        float var = qq * (1.0f / Dn) - mu * mu;
        float rs = rsqrtf(var + LN_EPS);
        s_mu[t] = mu;
        s_rs[t] = rs;
        g_mu[b * Ln + l0 + t] = mu;
        g_rsig[b * Ln + l0 + t] = rs;
        float mr = mu * rs;
        s_mr[t] = mr;
        s_m2[t] = mr * mr;
    }
    __syncthreads();
    int bc = blockIdx.x;
    if (t < 32) {
        float a = s_mr[t] + s_mr[32 + t];
        a = warpSum(a);
        if (t == 0) g_Psmr[bc] = a;
    } else if (t < 64) {
        int u = t - 32;
        float a = s_m2[u] + s_m2[32 + u];
        a = warpSum(a);
        if (u == 0) g_Ps22[bc] = a;
    }
    __syncthreads();

    int w = t >> 5, lane = t & 31;          // 16 warps
#pragma unroll
    for (int i = 0; i < 16; i++) {
        int d = i * 16 + w;
        float u1 = 0.f, u2 = 0.f, u3 = 0.f;
#pragma unroll
        for (int j = 0; j < 2; j++) {
            int l = j * 32 + lane;
            float x = tile[d * CH1 + l];
            float r = s_rs[l], a = s_mu[l];
            float xr = x * r;
            u1 += xr;
            u2 = fmaf(xr, xr, u2);
            u3 = fmaf(xr, a * r, u3);
        }
        u1 = warpSum(u1);
        u2 = warpSum(u2);
        u3 = warpSum(u3);
        if (lane == 0) {
            g_PU[(bc * 3 + 0) * Dn + d] = u1;
            g_PU[(bc * 3 + 1) * Dn + d] = u2;
            g_PU[(bc * 3 + 2) * Dn + d] = u3;
        }
    }
}

// ---------------- 2. per batch: reduce partials, batch mean/std, q, p ----------------
__global__ void k_qp(const float* __restrict__ wk, const float* __restrict__ wq,
                     const float* __restrict__ ln_g, const float* __restrict__ ln_b) {
    int b = blockIdx.x;
    int t = threadIdx.x;  // 256
    int w = t >> 5, lane = t & 31;
    __shared__ float ms[2 * Dn];
    __shared__ float qv[DKn];
    __shared__ float s_sc[2];

    float U1 = 0.f, U2 = 0.f, U3 = 0.f;
#pragma unroll 8
    for (int c = 0; c < NCH; c++) {
        int bc = b * NCH + c;
        U1 += g_PU[(bc * 3 + 0) * Dn + t];
        U2 += g_PU[(bc * 3 + 1) * Dn + t];
        U3 += g_PU[(bc * 3 + 2) * Dn + t];
    }
    if (w == 0) {
        float a = g_Psmr[b * NCH + lane] + g_Psmr[b * NCH + 32 + lane];
        a = warpSum(a);
        if (lane == 0) s_sc[0] = a;
    } else if (w == 1) {
        float a = g_Ps22[b * NCH + lane] + g_Ps22[b * NCH + 32 + lane];
        a = warpSum(a);
        if (lane == 0) s_sc[1] = a;
    }
    __syncthreads();
    float smr = s_sc[0], sm2r2 = s_sc[1];

    {
        int d = t;
        float g = ln_g[d], be = ln_b[d];
        float S1 = g * (U1 - smr) + (float)Ln * be;
        float S2 = g * g * (U2 - 2.0f * U3 + sm2r2) + 2.0f * g * be * (U1 - smr) + (float)Ln * be * be;
        float mean = S1 * (1.0f / Ln);
        float var = S2 * (1.0f / Ln) - mean * mean;
        float sd = sqrtf(fmaxf(var, EPS_CLIP));
        ms[d] = mean;
        ms[Dn + d] = sd;
    }
    __syncthreads();

#pragma unroll
    for (int i = 0; i < 16; i++) {
        int k = w * 16 + i;
        float acc = 0.f;
        const float* wr = wq + (size_t)k * 2 * Dn;
#pragma unroll
        for (int e = 0; e < 16; e++)
            acc = fmaf(wr[e * 32 + lane], ms[e * 32 + lane], acc);
        acc = warpSum(acc);
        if (lane == 0) qv[k] = acc;
    }
    __syncthreads();

    float p = 0.f;
#pragma unroll 8
    for (int k2 = 0; k2 < DKn; k2++) p = fmaf(wk[k2 * Dn + t], qv[k2], p);
    p *= rsqrtf((float)DKn);

    float gp = ln_g[t] * p;
    g_gp[b * Dn + t] = gp;
    float cb = bSum(ln_b[t] * p);
    float gpsum = bSum(gp);
    if (t == 0) { g_Cb[b] = cb; g_Gp[b] = gpsum; }
}

// ---------------- 3. scores: float4 over l, 2 d-halves per block ----------------
__global__ void __launch_bounds__(256) k_scores(const float* __restrict__ v) {
    __shared__ float sgp[Dn];
    __shared__ float4 red[128];
    int b = blockIdx.x >> 3;
    int seg = blockIdx.x & 7;
    int l0 = seg * 512;
    int t = threadIdx.x;
    int lv = t & 127;
    int dg = t >> 7;

    sgp[t] = g_gp[b * Dn + t];   // blockDim == Dn
    __syncthreads();

    const float* base = v + (size_t)b * Dn * Ln + l0 + lv * 4;
    float a0 = 0.f, a1 = 0.f, a2 = 0.f, a3 = 0.f;
#pragma unroll 8
    for (int dd = 0; dd < 128; dd++) {
        int d = dg * 128 + dd;
        float4 x = *reinterpret_cast<const float4*>(base + (size_t)d * Ln);
        float g = sgp[d];
        a0 = fmaf(x.x, g, a0);
        a1 = fmaf(x.y, g, a1);
        a2 = fmaf(x.z, g, a2);
        a3 = fmaf(x.w, g, a3);
    }
    if (dg == 1) red[lv] = make_float4(a0, a1, a2, a3);
    __syncthreads();
    if (dg == 0) {
        float4 o = red[lv];
        a0 += o.x; a1 += o.y; a2 += o.z; a3 += o.w;
        int li = b * Ln + l0 + lv * 4;
        float4 mu = *reinterpret_cast<const float4*>(&g_mu[li]);
        float4 rs = *reinterpret_cast<const float4*>(&g_rsig[li]);
        float Gp = g_Gp[b], Cb = g_Cb[b];
        float4 sc;
        sc.x = rs.x * (a0 - mu.x * Gp) + Cb;
        sc.y = rs.y * (a1 - mu.y * Gp) + Cb;
        sc.z = rs.z * (a2 - mu.z * Gp) + Cb;
        sc.w = rs.w * (a3 - mu.w * Gp) + Cb;
        *reinterpret_cast<float4*>(&g_scores[li]) = sc;
    }
}

// ---------------- 4. softmax over L per batch; also A, M2 ----------------
__global__ void k_softmax() {
    int b = blockIdx.x;
    int t = threadIdx.x;  // 1024
    float s[4];
    float m = -FLT_MAX;
#pragma unroll
    for (int i = 0; i < 4; i++) {
        s[i] = g_scores[b * Ln + i * 1024 + t];
        m = fmaxf(m, s[i]);
    }
    float M = bMax(m);
    float e[4];
    float se = 0.f, sar = 0.f, sa2 = 0.f;
#pragma unroll
    for (int i = 0; i < 4; i++) {
        e[i] = __expf(s[i] - M);
        se += e[i];
        int l = i * 1024 + t;
        float a = g_mu[b * Ln + l], r = g_rsig[b * Ln + l];
        sar = fmaf(e[i], a * r, sar);
        sa2 = fmaf(e[i], a * a * r * r, sa2);
    }
    float SE = bSum(se);
    float SAR = bSum(sar);
    float SA2 = bSum(sa2);
    float inv = 1.0f / SE;
#pragma unroll
    for (int i = 0; i < 4; i++) g_w[b * Ln + i * 1024 + t] = e[i] * inv;
    if (t == 0) { g_A[b] = SAR * inv; g_M2[b] = SA2 * inv; }
}

// ---------------- 5. weighted rowsums: 16 d's per block, coeffs in smem, float4 loads ----------------
__global__ void __launch_bounds__(512) k_attsums(const float* __restrict__ v) {
    __shared__ float c1[2048], c2[2048], c3[2048];
    int b = blockIdx.x >> 4;
    int dg = blockIdx.x & 15;
    int tid = threadIdx.x;            // 512
    int w = tid >> 5, lane = tid & 31;
    int d = dg * 16 + w;
    const float* vp = v + ((size_t)(b * Dn + d)) * Ln;
    const float* wp = g_w + b * Ln;
    const float* rp = g_rsig + b * Ln;
    const float* ap = g_mu + b * Ln;
    float s1 = 0.f, s2 = 0.f, s3 = 0.f;

#pragma unroll
    for (int chk = 0; chk < 2; chk++) {
        int lb = chk * 2048;
#pragma unroll
        for (int k = 0; k < 4; k++) {
            int l = lb + k * 512 + tid;
            float wg = wp[l], r = rp[l], a = ap[l];
            float cc1 = wg * r;
            float cc2 = cc1 * r;
            c1[k * 512 + tid] = cc1;
            c2[k * 512 + tid] = cc2;
            c3[k * 512 + tid] = cc2 * a;
        }
        __syncthreads();
#pragma unroll 4
        for (int j = 0; j < 16; j++) {
            int l = j * 128 + lane * 4;
            float4 x = *reinterpret_cast<const float4*>(vp + lb + l);
            float4 a1 = *reinterpret_cast<const float4*>(&c1[l]);
            float4 a2 = *reinterpret_cast<const float4*>(&c2[l]);
            float4 a3 = *reinterpret_cast<const float4*>(&c3[l]);
            s1 = fmaf(x.x, a1.x, s1); s1 = fmaf(x.y, a1.y, s1);
            s1 = fmaf(x.z, a1.z, s1); s1 = fmaf(x.w, a1.w, s1);
            s2 = fmaf(x.x * x.x, a2.x, s2); s2 = fmaf(x.y * x.y, a2.y, s2);
            s2 = fmaf(x.z * x.z, a2.z, s2); s2 = fmaf(x.w * x.w, a2.w, s2);
            s3 = fmaf(x.x, a3.x, s3); s3 = fmaf(x.y, a3.y, s3);
            s3 = fmaf(x.z, a3.z, s3); s3 = fmaf(x.w, a3.w, s3);
        }
        __syncthreads();
    }
    s1 = warpSum(s1);
    s2 = warpSum(s2);
    s3 = warpSum(s3);
    if (lane == 0) {
        int row = b * Dn + d;
        g_R1[row] = s1;
        g_R2[row] = s2;
        g_R3[row] = s3;
    }
}

// ---------------- 6. att stats -> corr + skip_conn (warp-coalesced matmuls) ----------------
__global__ void __launch_bounds__(256) k_finalize(const float* __restrict__ fcq_w,
                                                  const float* __restrict__ fc_w,
                                                  const float* __restrict__ fc_b,
                                                  const float* __restrict__ ln_g,
                                                  const float* __restrict__ ln_b,
                                                  float* __restrict__ out) {
    int b = blockIdx.x;
    int t = threadIdx.x;  // 256
    int w = t >> 5, lane = t & 31;
    __shared__ float am[Dn], as[Dn];
    {
        int d = t;
        float g = ln_g[d], be = ln_b[d];
        float R1 = g_R1[b * Dn + d], R2 = g_R2[b * Dn + d], R3 = g_R3[b * Dn + d];
        float A = g_A[b], M2 = g_M2[b];
        float mean = g * (R1 - A) + be;
        float E2 = g * g * (R2 - 2.0f * R3 + M2) + 2.0f * g * be * (R1 - A) + be * be;
        float var = E2 - mean * mean;
        am[d] = mean;
        as[d] = sqrtf(fmaxf(var, EPS_CLIP));
    }
    __syncthreads();

    // warp-per-output: each of 8 warps handles 32 outputs; lanes stride d (coalesced)
#pragma unroll
    for (int i = 0; i < 32; i++) {
        int o = w * 32 + i;
        const float* wr = fcq_w + (size_t)o * Dn;
        float c = 0.f;
#pragma unroll
        for (int e = 0; e < 8; e++)
            c = fmaf(wr[e * 32 + lane], am[e * 32 + lane], c);
        c = warpSum(c);

        const float* fr = fc_w + (size_t)o * 2 * Dn;
        float sk = 0.f;
#pragma unroll
        for (int e = 0; e < 8; e++) {
            sk = fmaf(fr[e * 32 + lane], am[e * 32 + lane], sk);
            sk = fmaf(fr[Dn + e * 32 + lane], as[e * 32 + lane], sk);
        }
        sk = warpSum(sk);

        if (lane == 0) {
            g_corr[b * Dn + o] = c;
            out[(size_t)Bn * Ln * Dn + b * Dn + o] = sk + fc_b[o];
        }
    }
}

// ---------------- 7. out1[b,l,o] = v[b,o,l] + corr[b,o]  (128l x 32o tile, streaming) ----------------
__global__ void k_out(const float* __restrict__ v, float* __restrict__ out) {
    __shared__ float tile[32 * 129];
    int b = blockIdx.z;
    int l0 = blockIdx.x * 128;
    int o0 = blockIdx.y * 32;
    int tid = threadIdx.x;          // 256
    int w = tid >> 5, lane = tid & 31;

#pragma unroll
    for (int i = 0; i < 4; i++) {
        int ol = w + 8 * i;
        int o = o0 + ol;
        float c = g_corr[b * Dn + o];
        const float4* vr = reinterpret_cast<const float4*>(v + ((size_t)(b * Dn + o)) * Ln + l0);
        float4 x = __ldcs(vr + lane);
        tile[ol * 129 + lane * 4 + 0] = x.x + c;
        tile[ol * 129 + lane * 4 + 1] = x.y + c;
        tile[ol * 129 + lane * 4 + 2] = x.z + c;
        tile[ol * 129 + lane * 4 + 3] = x.w + c;
    }
    __syncthreads();

    int o4 = tid & 7;
    int lq = tid >> 3;
#pragma unroll
    for (int i = 0; i < 4; i++) {
        int l = i * 32 + lq;
        float4 y;
        y.x = tile[(o4 * 4 + 0) * 129 + l];
        y.y = tile[(o4 * 4 + 1) * 129 + l];
        y.z = tile[(o4 * 4 + 2) * 129 + l];
        y.w = tile[(o4 * 4 + 3) * 129 + l];
        __stcs(reinterpret_cast<float4*>(out + ((size_t)b * Ln + l0 + l) * Dn + o0 + o4 * 4), y);
    }
}

// ---------------- launcher: full-width grids, single chain ----------------
extern "C" void kernel_launch(void* const* d_in, const int* in_sizes, int n_in,
                              void* d_out, int out_size) {
    const float* v     = (const float*)d_in[0];
    const float* ln_g  = (const float*)d_in[1];
    const float* ln_b  = (const float*)d_in[2];
    const float* wk    = (const float*)d_in[3];
    const float* wq    = (const float*)d_in[4];
    const float* fcq_w = (const float*)d_in[5];
    const float* fc_w  = (const float*)d_in[6];
    const float* fc_b  = (const float*)d_in[7];
    float* out = (float*)d_out;

    const int p1_smem = (Dn * CH1 + 4 * CH1 + 2 * 64 * 33) * 4;  // 83200 B
    cudaFuncSetAttribute(k_pass1, cudaFuncAttributeMaxDynamicSharedMemorySize, p1_smem);

    k_pass1<<<Bn * NCH, 512, p1_smem>>>(v);
    k_qp<<<Bn, 256>>>(wk, wq, ln_g, ln_b);
    k_scores<<<Bn * 8, 256>>>(v);
    k_softmax<<<Bn, 1024>>>();
    k_attsums<<<Bn * 16, 512>>>(v);
    k_finalize<<<Bn, 256>>>(fcq_w, fc_w, fc_b, ln_g, ln_b, out);
    k_out<<<dim3(Ln / 128, Dn / 32, Bn), 256>>>(v, out);
}

// round 8
// speedup vs baseline: 1.5945x; 1.2214x over previous
#include <cuda_runtime.h>
#include <cfloat>
#include <math.h>

#define Bn 64
#define Dn 256
#define Ln 4096
#define DKn 128
#define LN_EPS 1e-6f
#define EPS_CLIP 1e-10f

#define CH1 64                 // l-chunk per pass1 block
#define NCH (Ln / CH1)         // 64 chunks per batch

// ---------------- scratch (static device globals; no allocation) ----------------
__device__ float g_mu[Bn * Ln];
__device__ float g_rsig[Bn * Ln];
__device__ float g_scores[Bn * Ln];
__device__ float g_PU[Bn * NCH * 3 * Dn];   // per-chunk partials of U1,U2,U3
__device__ float g_Psmr[Bn * NCH];
__device__ float g_Ps22[Bn * NCH];
__device__ float g_R1[Bn * Dn], g_R2[Bn * Dn], g_R3[Bn * Dn];
__device__ float g_gp[Bn * Dn];
__device__ float g_corr[Bn * Dn];
__device__ float g_Cb[Bn], g_Gp[Bn], g_A[Bn], g_M2[Bn];

// ---------------- reduction helpers ----------------
__device__ __forceinline__ float warpSum(float v) {
#pragma unroll
    for (int o = 16; o; o >>= 1) v += __shfl_xor_sync(0xffffffffu, v, o);
    return v;
}
__device__ __forceinline__ float warpMax(float v) {
#pragma unroll
    for (int o = 16; o; o >>= 1) v = fmaxf(v, __shfl_xor_sync(0xffffffffu, v, o));
    return v;
}
__device__ __forceinline__ float bSum(float v) {
    __shared__ float sh[32];
    int lane = threadIdx.x & 31, w = threadIdx.x >> 5;
    int nw = (blockDim.x + 31) >> 5;
    v = warpSum(v);
    if (lane == 0) sh[w] = v;
    __syncthreads();
    if (w == 0) {
        float x = (lane < nw) ? sh[lane] : 0.0f;
        x = warpSum(x);
        if (lane == 0) sh[0] = x;
    }
    __syncthreads();
    float r = sh[0];
    __syncthreads();
    return r;
}
__device__ __forceinline__ float bMax(float v) {
    __shared__ float sh[32];
    int lane = threadIdx.x & 31, w = threadIdx.x >> 5;
    int nw = (blockDim.x + 31) >> 5;
    v = warpMax(v);
    if (lane == 0) sh[w] = v;
    __syncthreads();
    if (w == 0) {
        float x = (lane < nw) ? sh[lane] : -FLT_MAX;
        x = warpMax(x);
        if (lane == 0) sh[0] = x;
    }
    __syncthreads();
    float r = sh[0];
    __syncthreads();
    return r;
}

// ---------------- 1. fused LN stats + U-partials, REGISTER-resident (no tile) ----------------
// Block = (b, 64-l chunk), 512 threads. dg = t>>4 owns d = it*32+dg (8 rows), lv = t&15 owns l = lv*4..lv*4+3.
// Phase A: 8 float4 loads kept in registers; column sums via smem (stride-33).
// Phase B: per-d U-sums computed from registers, reduced across the 16 lv-lanes via shfl.
__global__ void __launch_bounds__(512) k_pass1(const float* __restrict__ v) {
    __shared__ float s_mu[CH1], s_rs[CH1], s_mr[CH1], s_m2[CH1];
    __shared__ float sA[64 * 33];
    __shared__ float sQ[64 * 33];

    int t = threadIdx.x;                    // 512
    int b = blockIdx.x >> 6;                // NCH == 64
    int ch = blockIdx.x & 63;
    int l0 = ch * CH1;
    int bc = blockIdx.x;
    int dg = t >> 4;                        // 0..31
    int lv = t & 15;

    const float* vbase = v + (size_t)b * Dn * Ln + l0 + lv * 4;
    float4 x[8];
    float cs0 = 0.f, cs1 = 0.f, cs2 = 0.f, cs3 = 0.f;
    float cq0 = 0.f, cq1 = 0.f, cq2 = 0.f, cq3 = 0.f;
#pragma unroll
    for (int it = 0; it < 8; it++) {
        int d = it * 32 + dg;
        x[it] = *reinterpret_cast<const float4*>(vbase + (size_t)d * Ln);
        cs0 += x[it].x; cs1 += x[it].y; cs2 += x[it].z; cs3 += x[it].w;
        cq0 = fmaf(x[it].x, x[it].x, cq0);
        cq1 = fmaf(x[it].y, x[it].y, cq1);
        cq2 = fmaf(x[it].z, x[it].z, cq2);
        cq3 = fmaf(x[it].w, x[it].w, cq3);
    }
    sA[(lv * 4 + 0) * 33 + dg] = cs0;
    sA[(lv * 4 + 1) * 33 + dg] = cs1;
    sA[(lv * 4 + 2) * 33 + dg] = cs2;
    sA[(lv * 4 + 3) * 33 + dg] = cs3;
    sQ[(lv * 4 + 0) * 33 + dg] = cq0;
    sQ[(lv * 4 + 1) * 33 + dg] = cq1;
    sQ[(lv * 4 + 2) * 33 + dg] = cq2;
    sQ[(lv * 4 + 3) * 33 + dg] = cq3;
    __syncthreads();

    if (t < CH1) {
        float ss = 0.f, qq = 0.f;
#pragma unroll
        for (int g = 0; g < 32; g++) {
            ss += sA[t * 33 + g];
            qq += sQ[t * 33 + g];
        }
        float mu = ss * (1.0f / Dn);
        float var = qq * (1.0f / Dn) - mu * mu;
        float rs = rsqrtf(var + LN_EPS);
        s_mu[t] = mu;
        s_rs[t] = rs;
        g_mu[b * Ln + l0 + t] = mu;
        g_rsig[b * Ln + l0 + t] = rs;
        float mr = mu * rs;
        s_mr[t] = mr;
        s_m2[t] = mr * mr;
    }
    __syncthreads();

    if (t < 32) {
        float a = s_mr[t] + s_mr[32 + t];
        a = warpSum(a);
        if (t == 0) g_Psmr[bc] = a;
    } else if (t < 64) {
        int u = t - 32;
        float a = s_m2[u] + s_m2[32 + u];
        a = warpSum(a);
        if (u == 0) g_Ps22[bc] = a;
    }

    // Phase B: from registers. r[j], am[j] = mu_j * r_j^2 for this thread's 4 l's.
    float r0 = s_rs[lv * 4 + 0], r1 = s_rs[lv * 4 + 1], r2 = s_rs[lv * 4 + 2], r3 = s_rs[lv * 4 + 3];
    float am0 = s_mu[lv * 4 + 0] * r0 * r0;
    float am1 = s_mu[lv * 4 + 1] * r1 * r1;
    float am2 = s_mu[lv * 4 + 2] * r2 * r2;
    float am3 = s_mu[lv * 4 + 3] * r3 * r3;

#pragma unroll
    for (int it = 0; it < 8; it++) {
        float4 xx = x[it];
        float xr0 = xx.x * r0, xr1 = xx.y * r1, xr2 = xx.z * r2, xr3 = xx.w * r3;
        float u1 = (xr0 + xr1) + (xr2 + xr3);
        float u2 = fmaf(xr0, xr0, fmaf(xr1, xr1, fmaf(xr2, xr2, xr3 * xr3)));
        float u3 = fmaf(xx.x, am0, fmaf(xx.y, am1, fmaf(xx.z, am2, xx.w * am3)));
#pragma unroll
        for (int o = 8; o; o >>= 1) {
            u1 += __shfl_down_sync(0xffffffffu, u1, o);
            u2 += __shfl_down_sync(0xffffffffu, u2, o);
            u3 += __shfl_down_sync(0xffffffffu, u3, o);
        }
        if (lv == 0) {
            int d = it * 32 + dg;
            g_PU[(bc * 3 + 0) * Dn + d] = u1;
            g_PU[(bc * 3 + 1) * Dn + d] = u2;
            g_PU[(bc * 3 + 2) * Dn + d] = u3;
        }
    }
}

// ---------------- 2. per batch: reduce partials, batch mean/std, q, p ----------------
__global__ void k_qp(const float* __restrict__ wk, const float* __restrict__ wq,
                     const float* __restrict__ ln_g, const float* __restrict__ ln_b) {
    int b = blockIdx.x;
    int t = threadIdx.x;  // 256
    int w = t >> 5, lane = t & 31;
    __shared__ float ms[2 * Dn];
    __shared__ float qv[DKn];
    __shared__ float s_sc[2];

    float U1 = 0.f, U2 = 0.f, U3 = 0.f;
#pragma unroll 8
    for (int c = 0; c < NCH; c++) {
        int bc = b * NCH + c;
        U1 += g_PU[(bc * 3 + 0) * Dn + t];
        U2 += g_PU[(bc * 3 + 1) * Dn + t];
        U3 += g_PU[(bc * 3 + 2) * Dn + t];
    }
    if (w == 0) {
        float a = g_Psmr[b * NCH + lane] + g_Psmr[b * NCH + 32 + lane];
        a = warpSum(a);
        if (lane == 0) s_sc[0] = a;
    } else if (w == 1) {
        float a = g_Ps22[b * NCH + lane] + g_Ps22[b * NCH + 32 + lane];
        a = warpSum(a);
        if (lane == 0) s_sc[1] = a;
    }
    __syncthreads();
    float smr = s_sc[0], sm2r2 = s_sc[1];

    {
        int d = t;
        float g = ln_g[d], be = ln_b[d];
        float S1 = g * (U1 - smr) + (float)Ln * be;
        float S2 = g * g * (U2 - 2.0f * U3 + sm2r2) + 2.0f * g * be * (U1 - smr) + (float)Ln * be * be;
        float mean = S1 * (1.0f / Ln);
        float var = S2 * (1.0f / Ln) - mean * mean;
        float sd = sqrtf(fmaxf(var, EPS_CLIP));
        ms[d] = mean;
        ms[Dn + d] = sd;
    }
    __syncthreads();

#pragma unroll
    for (int i = 0; i < 16; i++) {
        int k = w * 16 + i;
        float acc = 0.f;
        const float* wr = wq + (size_t)k * 2 * Dn;
#pragma unroll
        for (int e = 0; e < 16; e++)
            acc = fmaf(wr[e * 32 + lane], ms[e * 32 + lane], acc);
        acc = warpSum(acc);
        if (lane == 0) qv[k] = acc;
    }
    __syncthreads();

    float p = 0.f;
#pragma unroll 8
    for (int k2 = 0; k2 < DKn; k2++) p = fmaf(wk[k2 * Dn + t], qv[k2], p);
    p *= rsqrtf((float)DKn);

    float gp = ln_g[t] * p;
    g_gp[b * Dn + t] = gp;
    float cb = bSum(ln_b[t] * p);
    float gpsum = bSum(gp);
    if (t == 0) { g_Cb[b] = cb; g_Gp[b] = gpsum; }
}

// ---------------- 3. scores: float4 over l, 2 d-halves per block ----------------
__global__ void __launch_bounds__(256) k_scores(const float* __restrict__ v) {
    __shared__ float sgp[Dn];
    __shared__ float4 red[128];
    int b = blockIdx.x >> 3;
    int seg = blockIdx.x & 7;
    int l0 = seg * 512;
    int t = threadIdx.x;
    int lv = t & 127;
    int dg = t >> 7;

    sgp[t] = g_gp[b * Dn + t];   // blockDim == Dn
    __syncthreads();

    const float* base = v + (size_t)b * Dn * Ln + l0 + lv * 4;
    float a0 = 0.f, a1 = 0.f, a2 = 0.f, a3 = 0.f;
#pragma unroll 8
    for (int dd = 0; dd < 128; dd++) {
        int d = dg * 128 + dd;
        float4 x = *reinterpret_cast<const float4*>(base + (size_t)d * Ln);
        float g = sgp[d];
        a0 = fmaf(x.x, g, a0);
        a1 = fmaf(x.y, g, a1);
        a2 = fmaf(x.z, g, a2);
        a3 = fmaf(x.w, g, a3);
    }
    if (dg == 1) red[lv] = make_float4(a0, a1, a2, a3);
    __syncthreads();
    if (dg == 0) {
        float4 o = red[lv];
        a0 += o.x; a1 += o.y; a2 += o.z; a3 += o.w;
        int li = b * Ln + l0 + lv * 4;
        float4 mu = *reinterpret_cast<const float4*>(&g_mu[li]);
        float4 rs = *reinterpret_cast<const float4*>(&g_rsig[li]);
        float Gp = g_Gp[b], Cb = g_Cb[b];
        float4 sc;
        sc.x = rs.x * (a0 - mu.x * Gp) + Cb;
        sc.y = rs.y * (a1 - mu.y * Gp) + Cb;
        sc.z = rs.z * (a2 - mu.z * Gp) + Cb;
        sc.w = rs.w * (a3 - mu.w * Gp) + Cb;
        *reinterpret_cast<float4*>(&g_scores[li]) = sc;
    }
}

// ---------------- 4. attsums WITH integrated softmax ----------------
// Block = (b, 16-d group). Each block spans full L, so it computes the complete
// softmax normalization locally from g_scores (redundant across the 16 blocks of a batch).
__global__ void __launch_bounds__(512) k_attsums(const float* __restrict__ v) {
    extern __shared__ float cbuf[];     // c1[4096] | c2[4096] | c3[4096]
    float* c1 = cbuf;
    float* c2 = cbuf + Ln;
    float* c3 = cbuf + 2 * Ln;

    int b = blockIdx.x >> 4;
    int dg = blockIdx.x & 15;
    int tid = threadIdx.x;              // 512
    int w = tid >> 5, lane = tid & 31;

    const float* sp = g_scores + b * Ln;
    const float* rp = g_rsig + b * Ln;
    const float* ap = g_mu + b * Ln;

    // local softmax over full L
    float sv[8];
    float m = -FLT_MAX;
#pragma unroll
    for (int i = 0; i < 8; i++) {
        sv[i] = sp[i * 512 + tid];
        m = fmaxf(m, sv[i]);
    }
    float M = bMax(m);
    float se = 0.f, sar = 0.f, sa2 = 0.f;
#pragma unroll
    for (int i = 0; i < 8; i++) {
        int l = i * 512 + tid;
        float e = __expf(sv[i] - M);
        float r = rp[l], a = ap[l];
        float cc1 = e * r;
        float cc2 = cc1 * r;
        c1[l] = cc1;
        c2[l] = cc2;
        c3[l] = cc2 * a;
        se += e;
        float mr = a * r;
        sar = fmaf(e, mr, sar);
        sa2 = fmaf(e, mr * mr, sa2);
    }
    float SE = bSum(se);
    float SAR = bSum(sar);
    float SA2 = bSum(sa2);
    float inv = 1.0f / SE;
    if (tid == 0 && dg == 0) { g_A[b] = SAR * inv; g_M2[b] = SA2 * inv; }
    __syncthreads();

    // weighted row sums (16 d's, one per warp), float4 v + float4 smem coeffs
    int d = dg * 16 + w;
    const float* vp = v + ((size_t)(b * Dn + d)) * Ln;
    float s1 = 0.f, s2 = 0.f, s3 = 0.f;
#pragma unroll 4
    for (int j = 0; j < 32; j++) {
        int l = j * 128 + lane * 4;
        float4 x = *reinterpret_cast<const float4*>(vp + l);
        float4 a1 = *reinterpret_cast<const float4*>(&c1[l]);
        float4 a2 = *reinterpret_cast<const float4*>(&c2[l]);
        float4 a3 = *reinterpret_cast<const float4*>(&c3[l]);
        s1 = fmaf(x.x, a1.x, s1); s1 = fmaf(x.y, a1.y, s1);
        s1 = fmaf(x.z, a1.z, s1); s1 = fmaf(x.w, a1.w, s1);
        s2 = fmaf(x.x * x.x, a2.x, s2); s2 = fmaf(x.y * x.y, a2.y, s2);
        s2 = fmaf(x.z * x.z, a2.z, s2); s2 = fmaf(x.w * x.w, a2.w, s2);
        s3 = fmaf(x.x, a3.x, s3); s3 = fmaf(x.y, a3.y, s3);
        s3 = fmaf(x.z, a3.z, s3); s3 = fmaf(x.w, a3.w, s3);
    }
    s1 = warpSum(s1);
    s2 = warpSum(s2);
    s3 = warpSum(s3);
    if (lane == 0) {
        int row = b * Dn + d;
        g_R1[row] = s1 * inv;
        g_R2[row] = s2 * inv;
        g_R3[row] = s3 * inv;
    }
}

// ---------------- 5. att stats -> corr + skip_conn (warp-coalesced matmuls) ----------------
__global__ void __launch_bounds__(256) k_finalize(const float* __restrict__ fcq_w,
                                                  const float* __restrict__ fc_w,
                                                  const float* __restrict__ fc_b,
                                                  const float* __restrict__ ln_g,
                                                  const float* __restrict__ ln_b,
                                                  float* __restrict__ out) {
    int b = blockIdx.x;
    int t = threadIdx.x;  // 256
    int w = t >> 5, lane = t & 31;
    __shared__ float am[Dn], as[Dn];
    {
        int d = t;
        float g = ln_g[d], be = ln_b[d];
        float R1 = g_R1[b * Dn + d], R2 = g_R2[b * Dn + d], R3 = g_R3[b * Dn + d];
        float A = g_A[b], M2 = g_M2[b];
        float mean = g * (R1 - A) + be;
        float E2 = g * g * (R2 - 2.0f * R3 + M2) + 2.0f * g * be * (R1 - A) + be * be;
        float var = E2 - mean * mean;
        am[d] = mean;
        as[d] = sqrtf(fmaxf(var, EPS_CLIP));
    }
    __syncthreads();

#pragma unroll
    for (int i = 0; i < 32; i++) {
        int o = w * 32 + i;
        const float* wr = fcq_w + (size_t)o * Dn;
        float c = 0.f;
#pragma unroll
        for (int e = 0; e < 8; e++)
            c = fmaf(wr[e * 32 + lane], am[e * 32 + lane], c);
        c = warpSum(c);

        const float* fr = fc_w + (size_t)o * 2 * Dn;
        float sk = 0.f;
#pragma unroll
        for (int e = 0; e < 8; e++) {
            sk = fmaf(fr[e * 32 + lane], am[e * 32 + lane], sk);
            sk = fmaf(fr[Dn + e * 32 + lane], as[e * 32 + lane], sk);
        }
        sk = warpSum(sk);

        if (lane == 0) {
            g_corr[b * Dn + o] = c;
            out[(size_t)Bn * Ln * Dn + b * Dn + o] = sk + fc_b[o];
        }
    }
}

// ---------------- 6. out1[b,l,o] = v[b,o,l] + corr[b,o]  (128l x 32o tile, streaming) ----------------
__global__ void k_out(const float* __restrict__ v, float* __restrict__ out) {
    __shared__ float tile[32 * 129];
    int b = blockIdx.z;
    int l0 = blockIdx.x * 128;
    int o0 = blockIdx.y * 32;
    int tid = threadIdx.x;          // 256
    int w = tid >> 5, lane = tid & 31;

#pragma unroll
    for (int i = 0; i < 4; i++) {
        int ol = w + 8 * i;
        int o = o0 + ol;
        float c = g_corr[b * Dn + o];
        const float4* vr = reinterpret_cast<const float4*>(v + ((size_t)(b * Dn + o)) * Ln + l0);
        float4 x = __ldcs(vr + lane);
        tile[ol * 129 + lane * 4 + 0] = x.x + c;
        tile[ol * 129 + lane * 4 + 1] = x.y + c;
        tile[ol * 129 + lane * 4 + 2] = x.z + c;
        tile[ol * 129 + lane * 4 + 3] = x.w + c;
    }
    __syncthreads();

    int o4 = tid & 7;
    int lq = tid >> 3;
#pragma unroll
    for (int i = 0; i < 4; i++) {
        int l = i * 32 + lq;
        float4 y;
        y.x = tile[(o4 * 4 + 0) * 129 + l];
        y.y = tile[(o4 * 4 + 1) * 129 + l];
        y.z = tile[(o4 * 4 + 2) * 129 + l];
        y.w = tile[(o4 * 4 + 3) * 129 + l];
        __stcs(reinterpret_cast<float4*>(out + ((size_t)b * Ln + l0 + l) * Dn + o0 + o4 * 4), y);
    }
}

// ---------------- launcher: 6-kernel chain ----------------
extern "C" void kernel_launch(void* const* d_in, const int* in_sizes, int n_in,
                              void* d_out, int out_size) {
    const float* v     = (const float*)d_in[0];
    const float* ln_g  = (const float*)d_in[1];
    const float* ln_b  = (const float*)d_in[2];
    const float* wk    = (const float*)d_in[3];
    const float* wq    = (const float*)d_in[4];
    const float* fcq_w = (const float*)d_in[5];
    const float* fc_w  = (const float*)d_in[6];
    const float* fc_b  = (const float*)d_in[7];
    float* out = (float*)d_out;

    const int as_smem = 3 * Ln * 4;  // 49152 B dynamic for c1/c2/c3
    cudaFuncSetAttribute(k_attsums, cudaFuncAttributeMaxDynamicSharedMemorySize, as_smem);

    k_pass1<<<Bn * NCH, 512>>>(v);
    k_qp<<<Bn, 256>>>(wk, wq, ln_g, ln_b);
    k_scores<<<Bn * 8, 256>>>(v);
    k_attsums<<<Bn * 16, 512, as_smem>>>(v);
    k_finalize<<<Bn, 256>>>(fcq_w, fc_w, fc_b, ln_g, ln_b, out);
    k_out<<<dim3(Ln / 128, Dn / 32, Bn), 256>>>(v, out);
}

// round 9
// speedup vs baseline: 1.6375x; 1.0269x over previous
#include <cuda_runtime.h>
#include <cfloat>
#include <math.h>

#define Bn 64
#define Dn 256
#define Ln 4096
#define DKn 128
#define LN_EPS 1e-6f
#define EPS_CLIP 1e-10f

#define CH1 64                 // l-chunk per block
#define NCH (Ln / CH1)         // 64 chunks per batch

// ---------------- scratch (static device globals; no allocation) ----------------
__device__ float g_mu[Bn * Ln];
__device__ float g_rsig[Bn * Ln];
__device__ float g_PU[Bn * NCH * 3 * Dn];   // pass1 per-chunk partials U1,U2,U3
__device__ float g_PR[Bn * NCH * 3 * Dn];   // fused per-chunk partials R1,R2,R3 (unnormalized)
__device__ float g_Psmr[Bn * NCH];
__device__ float g_Ps22[Bn * NCH];
__device__ float g_Pml[Bn * NCH];           // chunk-local score max
__device__ float g_Pse[Bn * NCH];           // sum of e
__device__ float g_Pa[Bn * NCH];            // sum of e*mu*rsig
__device__ float g_Pm2[Bn * NCH];           // sum of e*(mu*rsig)^2
__device__ float g_gp[Bn * Dn];
__device__ float g_corr[Bn * Dn];
__device__ float g_Cb[Bn], g_Gp[Bn];

// ---------------- reduction helpers ----------------
__device__ __forceinline__ float warpSum(float v) {
#pragma unroll
    for (int o = 16; o; o >>= 1) v += __shfl_xor_sync(0xffffffffu, v, o);
    return v;
}
__device__ __forceinline__ float warpMax(float v) {
#pragma unroll
    for (int o = 16; o; o >>= 1) v = fmaxf(v, __shfl_xor_sync(0xffffffffu, v, o));
    return v;
}
__device__ __forceinline__ float bSum(float v) {
    __shared__ float sh[32];
    int lane = threadIdx.x & 31, w = threadIdx.x >> 5;
    int nw = (blockDim.x + 31) >> 5;
    v = warpSum(v);
    if (lane == 0) sh[w] = v;
    __syncthreads();
    if (w == 0) {
        float x = (lane < nw) ? sh[lane] : 0.0f;
        x = warpSum(x);
        if (lane == 0) sh[0] = x;
    }
    __syncthreads();
    float r = sh[0];
    __syncthreads();
    return r;
}

// ---------------- 1. fused LN stats + U-partials, REGISTER-resident ----------------
__global__ void __launch_bounds__(512) k_pass1(const float* __restrict__ v) {
    __shared__ float s_mu[CH1], s_rs[CH1], s_mr[CH1], s_m2[CH1];
    __shared__ float sA[64 * 33];
    __shared__ float sQ[64 * 33];

    int t = threadIdx.x;                    // 512
    int b = blockIdx.x >> 6;                // NCH == 64
    int ch = blockIdx.x & 63;
    int l0 = ch * CH1;
    int bc = blockIdx.x;
    int dg = t >> 4;                        // 0..31
    int lv = t & 15;

    const float* vbase = v + (size_t)b * Dn * Ln + l0 + lv * 4;
    float4 x[8];
    float cs0 = 0.f, cs1 = 0.f, cs2 = 0.f, cs3 = 0.f;
    float cq0 = 0.f, cq1 = 0.f, cq2 = 0.f, cq3 = 0.f;
#pragma unroll
    for (int it = 0; it < 8; it++) {
        int d = it * 32 + dg;
        x[it] = *reinterpret_cast<const float4*>(vbase + (size_t)d * Ln);
        cs0 += x[it].x; cs1 += x[it].y; cs2 += x[it].z; cs3 += x[it].w;
        cq0 = fmaf(x[it].x, x[it].x, cq0);
        cq1 = fmaf(x[it].y, x[it].y, cq1);
        cq2 = fmaf(x[it].z, x[it].z, cq2);
        cq3 = fmaf(x[it].w, x[it].w, cq3);
    }
    sA[(lv * 4 + 0) * 33 + dg] = cs0;
    sA[(lv * 4 + 1) * 33 + dg] = cs1;
    sA[(lv * 4 + 2) * 33 + dg] = cs2;
    sA[(lv * 4 + 3) * 33 + dg] = cs3;
    sQ[(lv * 4 + 0) * 33 + dg] = cq0;
    sQ[(lv * 4 + 1) * 33 + dg] = cq1;
    sQ[(lv * 4 + 2) * 33 + dg] = cq2;
    sQ[(lv * 4 + 3) * 33 + dg] = cq3;
    __syncthreads();

    if (t < CH1) {
        float ss = 0.f, qq = 0.f;
#pragma unroll
        for (int g = 0; g < 32; g++) {
            ss += sA[t * 33 + g];
            qq += sQ[t * 33 + g];
        }
        float mu = ss * (1.0f / Dn);
        float var = qq * (1.0f / Dn) - mu * mu;
        float rs = rsqrtf(var + LN_EPS);
        s_mu[t] = mu;
        s_rs[t] = rs;
        g_mu[b * Ln + l0 + t] = mu;
        g_rsig[b * Ln + l0 + t] = rs;
        float mr = mu * rs;
        s_mr[t] = mr;
        s_m2[t] = mr * mr;
    }
    __syncthreads();

    if (t < 32) {
        float a = s_mr[t] + s_mr[32 + t];
        a = warpSum(a);
        if (t == 0) g_Psmr[bc] = a;
    } else if (t < 64) {
        int u = t - 32;
        float a = s_m2[u] + s_m2[32 + u];
        a = warpSum(a);
        if (u == 0) g_Ps22[bc] = a;
    }

    float r0 = s_rs[lv * 4 + 0], r1 = s_rs[lv * 4 + 1], r2 = s_rs[lv * 4 + 2], r3 = s_rs[lv * 4 + 3];
    float am0 = s_mu[lv * 4 + 0] * r0 * r0;
    float am1 = s_mu[lv * 4 + 1] * r1 * r1;
    float am2 = s_mu[lv * 4 + 2] * r2 * r2;
    float am3 = s_mu[lv * 4 + 3] * r3 * r3;

#pragma unroll
    for (int it = 0; it < 8; it++) {
        float4 xx = x[it];
        float xr0 = xx.x * r0, xr1 = xx.y * r1, xr2 = xx.z * r2, xr3 = xx.w * r3;
        float u1 = (xr0 + xr1) + (xr2 + xr3);
        float u2 = fmaf(xr0, xr0, fmaf(xr1, xr1, fmaf(xr2, xr2, xr3 * xr3)));
        float u3 = fmaf(xx.x, am0, fmaf(xx.y, am1, fmaf(xx.z, am2, xx.w * am3)));
#pragma unroll
        for (int o = 8; o; o >>= 1) {
            u1 += __shfl_down_sync(0xffffffffu, u1, o);
            u2 += __shfl_down_sync(0xffffffffu, u2, o);
            u3 += __shfl_down_sync(0xffffffffu, u3, o);
        }
        if (lv == 0) {
            int d = it * 32 + dg;
            g_PU[(bc * 3 + 0) * Dn + d] = u1;
            g_PU[(bc * 3 + 1) * Dn + d] = u2;
            g_PU[(bc * 3 + 2) * Dn + d] = u3;
        }
    }
}

// ---------------- 2. per batch: reduce partials, batch mean/std, q, p ----------------
__global__ void k_qp(const float* __restrict__ wk, const float* __restrict__ wq,
                     const float* __restrict__ ln_g, const float* __restrict__ ln_b) {
    int b = blockIdx.x;
    int t = threadIdx.x;  // 256
    int w = t >> 5, lane = t & 31;
    __shared__ float ms[2 * Dn];
    __shared__ float qv[DKn];
    __shared__ float s_sc[2];

    float U1 = 0.f, U2 = 0.f, U3 = 0.f;
#pragma unroll 8
    for (int c = 0; c < NCH; c++) {
        int bc = b * NCH + c;
        U1 += g_PU[(bc * 3 + 0) * Dn + t];
        U2 += g_PU[(bc * 3 + 1) * Dn + t];
        U3 += g_PU[(bc * 3 + 2) * Dn + t];
    }
    if (w == 0) {
        float a = g_Psmr[b * NCH + lane] + g_Psmr[b * NCH + 32 + lane];
        a = warpSum(a);
        if (lane == 0) s_sc[0] = a;
    } else if (w == 1) {
        float a = g_Ps22[b * NCH + lane] + g_Ps22[b * NCH + 32 + lane];
        a = warpSum(a);
        if (lane == 0) s_sc[1] = a;
    }
    __syncthreads();
    float smr = s_sc[0], sm2r2 = s_sc[1];

    {
        int d = t;
        float g = ln_g[d], be = ln_b[d];
        float S1 = g * (U1 - smr) + (float)Ln * be;
        float S2 = g * g * (U2 - 2.0f * U3 + sm2r2) + 2.0f * g * be * (U1 - smr) + (float)Ln * be * be;
        float mean = S1 * (1.0f / Ln);
        float var = S2 * (1.0f / Ln) - mean * mean;
        float sd = sqrtf(fmaxf(var, EPS_CLIP));
        ms[d] = mean;
        ms[Dn + d] = sd;
    }
    __syncthreads();

#pragma unroll
    for (int i = 0; i < 16; i++) {
        int k = w * 16 + i;
        float acc = 0.f;
        const float* wr = wq + (size_t)k * 2 * Dn;
#pragma unroll
        for (int e = 0; e < 16; e++)
            acc = fmaf(wr[e * 32 + lane], ms[e * 32 + lane], acc);
        acc = warpSum(acc);
        if (lane == 0) qv[k] = acc;
    }
    __syncthreads();

    float p = 0.f;
#pragma unroll 8
    for (int k2 = 0; k2 < DKn; k2++) p = fmaf(wk[k2 * Dn + t], qv[k2], p);
    p *= rsqrtf((float)DKn);

    float gp = ln_g[t] * p;
    g_gp[b * Dn + t] = gp;
    float cb = bSum(ln_b[t] * p);
    float gpsum = bSum(gp);
    if (t == 0) { g_Cb[b] = cb; g_Gp[b] = gpsum; }
}

// ---------------- 3. FUSED scores + chunk-local softmax + weighted partials (register-resident) ----------------
// Block = (b, 64-l chunk), 512 threads; v tile held in registers (8 float4 per thread).
__global__ void __launch_bounds__(512) k_fused(const float* __restrict__ v) {
    __shared__ float s_gp[Dn];
    __shared__ float s_mu[CH1], s_rs[CH1];
    __shared__ float s_c1[CH1], s_c2[CH1], s_c3[CH1];
    __shared__ float s_s[CH1];
    __shared__ float s_ml[1];
    __shared__ float sA[64 * 33];

    int t = threadIdx.x;                    // 512
    int b = blockIdx.x >> 6;
    int ch = blockIdx.x & 63;
    int l0 = ch * CH1;
    int bc = blockIdx.x;
    int dg = t >> 4;                        // 0..31
    int lv = t & 15;

    if (t < Dn) s_gp[t] = g_gp[b * Dn + t];
    if (t >= 256 && t < 320) s_mu[t - 256] = g_mu[b * Ln + l0 + (t - 256)];
    if (t >= 320 && t < 384) s_rs[t - 320] = g_rsig[b * Ln + l0 + (t - 320)];
    __syncthreads();

    // Phase A: load 8 float4 into registers, accumulate per-l dot partials
    const float* vbase = v + (size_t)b * Dn * Ln + l0 + lv * 4;
    float4 x[8];
    float a0 = 0.f, a1 = 0.f, a2 = 0.f, a3 = 0.f;
#pragma unroll
    for (int it = 0; it < 8; it++) {
        int d = it * 32 + dg;
        x[it] = *reinterpret_cast<const float4*>(vbase + (size_t)d * Ln);
        float g = s_gp[d];
        a0 = fmaf(x[it].x, g, a0);
        a1 = fmaf(x[it].y, g, a1);
        a2 = fmaf(x[it].z, g, a2);
        a3 = fmaf(x[it].w, g, a3);
    }
    sA[(lv * 4 + 0) * 33 + dg] = a0;
    sA[(lv * 4 + 1) * 33 + dg] = a1;
    sA[(lv * 4 + 2) * 33 + dg] = a2;
    sA[(lv * 4 + 3) * 33 + dg] = a3;
    __syncthreads();

    if (t < CH1) {
        float dot = 0.f;
#pragma unroll
        for (int g = 0; g < 32; g++) dot += sA[t * 33 + g];
        s_s[t] = s_rs[t] * (dot - s_mu[t] * g_Gp[b]) + g_Cb[b];
    }
    __syncthreads();

    if (t < 32) {
        float m = fmaxf(s_s[t], s_s[32 + t]);
        m = warpMax(m);
        if (t == 0) { s_ml[0] = m; g_Pml[bc] = m; }
    }
    __syncthreads();

    if (t < CH1) {
        float e = __expf(s_s[t] - s_ml[0]);
        float rs = s_rs[t], mu = s_mu[t];
        float c1 = e * rs;
        float c2 = c1 * rs;
        s_c1[t] = c1;
        s_c2[t] = c2;
        s_c3[t] = c2 * mu;
        float mr = mu * rs;
        sA[t] = e;
        sA[64 + t] = e * mr;
        sA[128 + t] = e * mr * mr;
    }
    __syncthreads();
    if (t < 32) {
        float a = sA[t] + sA[32 + t];
        a = warpSum(a);
        if (t == 0) g_Pse[bc] = a;
    } else if (t < 64) {
        int u = t - 32;
        float a = sA[64 + u] + sA[96 + u];
        a = warpSum(a);
        if (u == 0) g_Pa[bc] = a;
    } else if (t < 96) {
        int u = t - 64;
        float a = sA[128 + u] + sA[160 + u];
        a = warpSum(a);
        if (u == 0) g_Pm2[bc] = a;
    }
    __syncthreads();

    // Phase B: per-d weighted partials from registers
    float c10 = s_c1[lv * 4 + 0], c11 = s_c1[lv * 4 + 1], c12 = s_c1[lv * 4 + 2], c13 = s_c1[lv * 4 + 3];
    float c20 = s_c2[lv * 4 + 0], c21 = s_c2[lv * 4 + 1], c22 = s_c2[lv * 4 + 2], c23 = s_c2[lv * 4 + 3];
    float c30 = s_c3[lv * 4 + 0], c31 = s_c3[lv * 4 + 1], c32 = s_c3[lv * 4 + 2], c33 = s_c3[lv * 4 + 3];

#pragma unroll
    for (int it = 0; it < 8; it++) {
        float4 xx = x[it];
        float r1 = fmaf(xx.x, c10, fmaf(xx.y, c11, fmaf(xx.z, c12, xx.w * c13)));
        float r2 = fmaf(xx.x * xx.x, c20, fmaf(xx.y * xx.y, c21,
                   fmaf(xx.z * xx.z, c22, (xx.w * xx.w) * c23)));
        float r3 = fmaf(xx.x, c30, fmaf(xx.y, c31, fmaf(xx.z, c32, xx.w * c33)));
#pragma unroll
        for (int o = 8; o; o >>= 1) {
            r1 += __shfl_down_sync(0xffffffffu, r1, o);
            r2 += __shfl_down_sync(0xffffffffu, r2, o);
            r3 += __shfl_down_sync(0xffffffffu, r3, o);
        }
        if (lv == 0) {
            int d = it * 32 + dg;
            g_PR[(bc * 3 + 0) * Dn + d] = r1;
            g_PR[(bc * 3 + 1) * Dn + d] = r2;
            g_PR[(bc * 3 + 2) * Dn + d] = r3;
        }
    }
}

// ---------------- 4. flash combine + att stats -> corr + skip_conn ----------------
__global__ void __launch_bounds__(256) k_finalize(const float* __restrict__ fcq_w,
                                                  const float* __restrict__ fc_w,
                                                  const float* __restrict__ fc_b,
                                                  const float* __restrict__ ln_g,
                                                  const float* __restrict__ ln_b,
                                                  float* __restrict__ out) {
    int b = blockIdx.x;
    int t = threadIdx.x;  // 256
    int w = t >> 5, lane = t & 31;
    __shared__ float s_scale[NCH];
    __shared__ float s_M[1];
    __shared__ float am[Dn], as[Dn];

    if (t < 32) {
        float m = fmaxf(g_Pml[b * NCH + t], g_Pml[b * NCH + 32 + t]);
        m = warpMax(m);
        if (t == 0) s_M[0] = m;
    }
    __syncthreads();
    if (t < NCH) s_scale[t] = __expf(g_Pml[b * NCH + t] - s_M[0]);
    __syncthreads();

    float R1 = 0.f, R2 = 0.f, R3 = 0.f;
#pragma unroll 8
    for (int c = 0; c < NCH; c++) {
        int bc = b * NCH + c;
        float sc = s_scale[c];
        R1 = fmaf(g_PR[(bc * 3 + 0) * Dn + t], sc, R1);
        R2 = fmaf(g_PR[(bc * 3 + 1) * Dn + t], sc, R2);
        R3 = fmaf(g_PR[(bc * 3 + 2) * Dn + t], sc, R3);
    }
    float se_p = (t < NCH) ? g_Pse[b * NCH + t] * s_scale[t] : 0.f;
    float a_p  = (t < NCH) ? g_Pa[b * NCH + t] * s_scale[t] : 0.f;
    float m2_p = (t < NCH) ? g_Pm2[b * NCH + t] * s_scale[t] : 0.f;
    float SE = bSum(se_p);
    float Asum = bSum(a_p);
    float M2sum = bSum(m2_p);
    float inv = 1.0f / SE;
    float A = Asum * inv, M2 = M2sum * inv;
    R1 *= inv; R2 *= inv; R3 *= inv;

    {
        int d = t;
        float g = ln_g[d], be = ln_b[d];
        float mean = g * (R1 - A) + be;
        float E2 = g * g * (R2 - 2.0f * R3 + M2) + 2.0f * g * be * (R1 - A) + be * be;
        float var = E2 - mean * mean;
        am[d] = mean;
        as[d] = sqrtf(fmaxf(var, EPS_CLIP));
    }
    __syncthreads();

#pragma unroll
    for (int i = 0; i < 32; i++) {
        int o = w * 32 + i;
        const float* wr = fcq_w + (size_t)o * Dn;
        float c = 0.f;
#pragma unroll
        for (int e = 0; e < 8; e++)
            c = fmaf(wr[e * 32 + lane], am[e * 32 + lane], c);
        c = warpSum(c);

        const float* fr = fc_w + (size_t)o * 2 * Dn;
        float sk = 0.f;
#pragma unroll
        for (int e = 0; e < 8; e++) {
            sk = fmaf(fr[e * 32 + lane], am[e * 32 + lane], sk);
            sk = fmaf(fr[Dn + e * 32 + lane], as[e * 32 + lane], sk);
        }
        sk = warpSum(sk);

        if (lane == 0) {
            g_corr[b * Dn + o] = c;
            out[(size_t)Bn * Ln * Dn + b * Dn + o] = sk + fc_b[o];
        }
    }
}

// ---------------- 5. out1[b,l,o] = v[b,o,l] + corr[b,o]  (128l x 32o tile, streaming) ----------------
__global__ void k_out(const float* __restrict__ v, float* __restrict__ out) {
    __shared__ float tile[32 * 129];
    int b = blockIdx.z;
    int l0 = blockIdx.x * 128;
    int o0 = blockIdx.y * 32;
    int tid = threadIdx.x;          // 256
    int w = tid >> 5, lane = tid & 31;

#pragma unroll
    for (int i = 0; i < 4; i++) {
        int ol = w + 8 * i;
        int o = o0 + ol;
        float c = g_corr[b * Dn + o];
        const float4* vr = reinterpret_cast<const float4*>(v + ((size_t)(b * Dn + o)) * Ln + l0);
        float4 x = __ldcs(vr + lane);
        tile[ol * 129 + lane * 4 + 0] = x.x + c;
        tile[ol * 129 + lane * 4 + 1] = x.y + c;
        tile[ol * 129 + lane * 4 + 2] = x.z + c;
        tile[ol * 129 + lane * 4 + 3] = x.w + c;
    }
    __syncthreads();

    int o4 = tid & 7;
    int lq = tid >> 3;
#pragma unroll
    for (int i = 0; i < 4; i++) {
        int l = i * 32 + lq;
        float4 y;
        y.x = tile[(o4 * 4 + 0) * 129 + l];
        y.y = tile[(o4 * 4 + 1) * 129 + l];
        y.z = tile[(o4 * 4 + 2) * 129 + l];
        y.w = tile[(o4 * 4 + 3) * 129 + l];
        __stcs(reinterpret_cast<float4*>(out + ((size_t)b * Ln + l0 + l) * Dn + o0 + o4 * 4), y);
    }
}

// ---------------- launcher: 5-kernel chain, 3 v-reads + 1 write total ----------------
extern "C" void kernel_launch(void* const* d_in, const int* in_sizes, int n_in,
                              void* d_out, int out_size) {
    const float* v     = (const float*)d_in[0];
    const float* ln_g  = (const float*)d_in[1];
    const float* ln_b  = (const float*)d_in[2];
    const float* wk    = (const float*)d_in[3];
    const float* wq    = (const float*)d_in[4];
    const float* fcq_w = (const float*)d_in[5];
    const float* fc_w  = (const float*)d_in[6];
    const float* fc_b  = (const float*)d_in[7];
    float* out = (float*)d_out;

    k_pass1<<<Bn * NCH, 512>>>(v);
    k_qp<<<Bn, 256>>>(wk, wq, ln_g, ln_b);
    k_fused<<<Bn * NCH, 512>>>(v);
    k_finalize<<<Bn, 256>>>(fcq_w, fc_w, fc_b, ln_g, ln_b, out);
    k_out<<<dim3(Ln / 128, Dn / 32, Bn), 256>>>(v, out);
}